// round 16
// baseline (speedup 1.0000x reference)
#include <cuda_runtime.h>
#include <cuda_fp16.h>
#include <cstdint>
#include <math.h>

#define Bsz 4096
#define Asz 4096
#define Hsz 768
#define Lsz 4
#define G3H (3 * Hsz)   // 2304
#define CAND_COLS 32    // head n-tiles (4096/128)

#define GUMBEL_PARTITIONABLE 1

// ======================= device scratch ===================================
__device__ __half d_wih_hi[(size_t)G3H * Hsz];
__device__ __half d_wih_lo[(size_t)G3H * Hsz];
__device__ __half d_whh_hi[(size_t)G3H * Hsz];
__device__ __half d_whh_lo[(size_t)G3H * Hsz];
__device__ __half d_hw_hi[(size_t)Asz * Hsz];
__device__ __half d_hw_lo[(size_t)Asz * Hsz];
__device__ __half d_a_hi[(size_t)Asz * Hsz];    // aew split, then h split
__device__ __half d_a_lo[(size_t)Asz * Hsz];
__device__ __half d_cls_hi[(size_t)Bsz * Hsz];  // cls split
__device__ __half d_cls_lo[(size_t)Bsz * Hsz];
__device__ float d_Gcls[(size_t)Bsz * G3H];
__device__ float d_AEp[(size_t)Asz * G3H];
__device__ float d_gh[(size_t)Bsz * G3H];
__device__ float d_h[(size_t)Bsz * Hsz];
__device__ unsigned long long d_cand[(size_t)Bsz * CAND_COLS];
__device__ unsigned int d_mask[(size_t)Bsz * Asz / 32];
__device__ int d_idx[Lsz * Bsz];
__device__ unsigned int d_qcounter[8];   // persistent-GEMM work queues

// ======================= threefry2x32 =====================================
__host__ __device__ __forceinline__ void threefry2x32(
    unsigned int k0, unsigned int k1, unsigned int x0, unsigned int x1,
    unsigned int& o0, unsigned int& o1)
{
    unsigned int ks0 = k0, ks1 = k1, ks2 = k0 ^ k1 ^ 0x1BD11BDAu;
    x0 += ks0; x1 += ks1;
#define TF_RND(r) { x0 += x1; x1 = (x1 << (r)) | (x1 >> (32 - (r))); x1 ^= x0; }
    TF_RND(13) TF_RND(15) TF_RND(26) TF_RND(6)
    x0 += ks1; x1 += ks2 + 1u;
    TF_RND(17) TF_RND(29) TF_RND(16) TF_RND(24)
    x0 += ks2; x1 += ks0 + 2u;
    TF_RND(13) TF_RND(15) TF_RND(26) TF_RND(6)
    x0 += ks0; x1 += ks1 + 3u;
    TF_RND(17) TF_RND(29) TF_RND(16) TF_RND(24)
    x0 += ks1; x1 += ks2 + 4u;
    TF_RND(13) TF_RND(15) TF_RND(26) TF_RND(6)
    x0 += ks2; x1 += ks0 + 5u;
#undef TF_RND
    o0 = x0; o1 = x1;
}

// gumbel value for flat position p = b*Asz + a  (bit-identical to reference)
__device__ __forceinline__ float gumbel_at(unsigned long long p,
                                           unsigned int sk0, unsigned int sk1)
{
    unsigned int y0, y1, bits;
#if GUMBEL_PARTITIONABLE
    threefry2x32(sk0, sk1, (unsigned int)(p >> 32), (unsigned int)p, y0, y1);
    bits = y0 ^ y1;
#else
    const unsigned long long NH = (unsigned long long)Bsz * Asz / 2;
    if (p < NH) { threefry2x32(sk0, sk1, (unsigned int)p, (unsigned int)(p + NH), y0, y1); bits = y0; }
    else        { threefry2x32(sk0, sk1, (unsigned int)(p - NH), (unsigned int)p, y0, y1); bits = y1; }
#endif
    float u = __uint_as_float((bits >> 9) | 0x3f800000u) - 1.0f;
    u = fmaxf(u, 1.17549435e-38f);
    return -logf(-logf(u));
}

__device__ __forceinline__ unsigned int ford(float f)
{
    unsigned int u = __float_as_uint(f);
    return (u & 0x80000000u) ? ~u : (u | 0x80000000u);
}

// ======================= fp16 hi/lo split =================================
__device__ __forceinline__ void split_f16(float x, __half& hi, __half& lo)
{
    __half h = __float2half_rn(x);
    float hf = __half2float(h);
    hi = h;
    lo = __float2half_rn(x - hf);
}

// ======================= fp16x2 mma.sync GEMM (LDSM frags) ================
#define BM 128
#define BN 128
#define BKc 16
#define NSTG 4
#define LDW 12                          // smem row stride words (48 B)
#define AST (128 * LDW * 4)             // 6144 B per array per stage
#define STG_BYTES (4 * AST)             // 24576 B
#define GEMM_SMEM (NSTG * STG_BYTES)    // 98304 B
#define NPERSIST 296                    // 148 SMs x 2 CTAs

#define CP_ASYNC16(dst_u32, src_ptr) \
    asm volatile("cp.async.cg.shared.global [%0], [%1], 16;" :: "r"(dst_u32), "l"(src_ptr) : "memory")
#define CP_COMMIT() asm volatile("cp.async.commit_group;" ::: "memory")
#define CP_WAIT(n)  asm volatile("cp.async.wait_group %0;" :: "n"(n) : "memory")

#define LDSM_X4(r0, r1, r2, r3, addr) \
    asm volatile("ldmatrix.sync.aligned.m8n8.x4.shared.b16 {%0,%1,%2,%3}, [%4];" \
        : "=r"(r0), "=r"(r1), "=r"(r2), "=r"(r3) : "r"(addr))

#define MMA_F16(c, a, b) \
    asm("mma.sync.aligned.m16n8k16.row.col.f32.f16.f16.f32 " \
        "{%0,%1,%2,%3}, {%4,%5,%6,%7}, {%8,%9}, {%0,%1,%2,%3};" \
        : "+f"((c)[0]), "+f"((c)[1]), "+f"((c)[2]), "+f"((c)[3]) \
        : "r"((a)[0]), "r"((a)[1]), "r"((a)[2]), "r"((a)[3]), \
          "r"((b)[0]), "r"((b)[1]))

// cand == nullptr: normal epilogue (C + bias).
// cand != nullptr: fused gumbel+argmax epilogue -> d_cand[row][candCol].
__device__ __forceinline__ void gemm_core(
    const __half* __restrict__ Ahi, const __half* __restrict__ Alo,
    const __half* __restrict__ Bhi, const __half* __restrict__ Blo,
    const float* __restrict__ bias, float* __restrict__ C,
    int N, int K, int bm, int bn, char* smraw,
    unsigned long long* cand, int candCol, const float* __restrict__ x_,
    int j, unsigned int sk0, unsigned int sk1)
{
    const int tid = threadIdx.x;
    const int wid = tid >> 5, lane = tid & 31;
    const int wm = wid >> 1;
    const int wn = wid & 1;
    const int g = lane >> 2;
    const int tg = lane & 3;
    const int NC = K / BKc;

    uint32_t smb;
    asm("{ .reg .u64 t; cvta.to.shared.u64 t, %1; cvt.u32.u64 %0, t; }"
        : "=r"(smb) : "l"(smraw));

    const uint32_t aBase = smb
        + (uint32_t)((wm * 32 + (lane & 15)) * (LDW * 4))
        + (uint32_t)((lane >> 4) * 16);
    const uint32_t bBase = smb + 2 * AST
        + (uint32_t)((wn * 64 + ((lane >> 4) << 3) + (lane & 7)) * (LDW * 4))
        + (uint32_t)(((lane >> 3) & 1) << 4);

    float acc[2][8][4];
#pragma unroll
    for (int i = 0; i < 2; i++)
#pragma unroll
        for (int jj = 0; jj < 8; jj++)
#pragma unroll
            for (int k = 0; k < 4; k++) acc[i][jj][k] = 0.f;

    const int rr = tid >> 1;
    const int qq = tid & 1;

#pragma unroll
    for (int pc = 0; pc < 2; pc++) {
        const int k0 = pc * BKc;
        const uint32_t sbase = smb + pc * STG_BYTES + (uint32_t)(rr * (LDW * 4) + qq * 16);
        const size_t ga = (size_t)(bm + rr) * K + k0 + qq * 8;
        const size_t gb = (size_t)(bn + rr) * K + k0 + qq * 8;
        CP_ASYNC16(sbase,           Ahi + ga);
        CP_ASYNC16(sbase + AST,     Alo + ga);
        CP_ASYNC16(sbase + 2 * AST, Bhi + gb);
        CP_ASYNC16(sbase + 3 * AST, Blo + gb);
        CP_COMMIT();
    }

    for (int c = 0; c < NC; ++c) {
        if (c + 2 < NC) {
            const int k0 = (c + 2) * BKc;
            const int st = (c + 2) & 3;
            const uint32_t sbase = smb + st * STG_BYTES + (uint32_t)(rr * (LDW * 4) + qq * 16);
            const size_t ga = (size_t)(bm + rr) * K + k0 + qq * 8;
            const size_t gb = (size_t)(bn + rr) * K + k0 + qq * 8;
            CP_ASYNC16(sbase,           Ahi + ga);
            CP_ASYNC16(sbase + AST,     Alo + ga);
            CP_ASYNC16(sbase + 2 * AST, Bhi + gb);
            CP_ASYNC16(sbase + 3 * AST, Blo + gb);
            CP_COMMIT();
            CP_WAIT(2);
        } else if (c + 2 == NC) {
            CP_WAIT(1);
        } else {
            CP_WAIT(0);
        }
        __syncthreads();

        const uint32_t stOff = (uint32_t)((c & 3) * STG_BYTES);
        const uint32_t aA = aBase + stOff;
        const uint32_t bA = bBase + stOff;

        uint32_t ahi[2][4], alo[2][4];
        LDSM_X4(ahi[0][0], ahi[0][1], ahi[0][2], ahi[0][3], aA);
        LDSM_X4(ahi[1][0], ahi[1][1], ahi[1][2], ahi[1][3], aA + 16 * (LDW * 4));
        LDSM_X4(alo[0][0], alo[0][1], alo[0][2], alo[0][3], aA + AST);
        LDSM_X4(alo[1][0], alo[1][1], alo[1][2], alo[1][3], aA + AST + 16 * (LDW * 4));

#pragma unroll
        for (int hb = 0; hb < 2; hb++) {
            uint32_t bhi[4][2], blo[4][2];
            const uint32_t bh0 = bA + (uint32_t)(hb * 32 * (LDW * 4));
            LDSM_X4(bhi[0][0], bhi[0][1], bhi[1][0], bhi[1][1], bh0);
            LDSM_X4(bhi[2][0], bhi[2][1], bhi[3][0], bhi[3][1], bh0 + 16 * (LDW * 4));
            LDSM_X4(blo[0][0], blo[0][1], blo[1][0], blo[1][1], bh0 + AST);
            LDSM_X4(blo[2][0], blo[2][1], blo[3][0], blo[3][1], bh0 + AST + 16 * (LDW * 4));
#pragma unroll
            for (int mt = 0; mt < 2; mt++)
#pragma unroll
                for (int nt = 0; nt < 4; nt++)
                    MMA_F16(acc[mt][hb * 4 + nt], ahi[mt], blo[nt]);
#pragma unroll
            for (int mt = 0; mt < 2; mt++)
#pragma unroll
                for (int nt = 0; nt < 4; nt++)
                    MMA_F16(acc[mt][hb * 4 + nt], alo[mt], bhi[nt]);
#pragma unroll
            for (int mt = 0; mt < 2; mt++)
#pragma unroll
                for (int nt = 0; nt < 4; nt++)
                    MMA_F16(acc[mt][hb * 4 + nt], ahi[mt], bhi[nt]);
        }
    }

    if (cand == nullptr) {
        // ---- normal epilogue ----
#pragma unroll
        for (int mt = 0; mt < 2; mt++) {
            const int r0 = bm + wm * 32 + mt * 16 + g;
#pragma unroll
            for (int nt = 0; nt < 8; nt++) {
                const int n0 = bn + wn * 64 + nt * 8 + tg * 2;
                float bx = 0.f, by = 0.f;
                if (bias) { bx = bias[n0]; by = bias[n0 + 1]; }
                float2 v0 = make_float2(acc[mt][nt][0] + bx, acc[mt][nt][1] + by);
                float2 v1 = make_float2(acc[mt][nt][2] + bx, acc[mt][nt][3] + by);
                *(float2*)(C + (size_t)r0 * N + n0) = v0;
                *(float2*)(C + (size_t)(r0 + 8) * N + n0) = v1;
            }
        }
    } else {
        // ---- fused gumbel + masked argmax epilogue (proven in R11) ----
#pragma unroll
        for (int mt = 0; mt < 2; mt++) {
#pragma unroll
            for (int rh = 0; rh < 2; rh++) {
                const int brow = bm + wm * 32 + mt * 16 + g + rh * 8;
                const float* xr = x_ + (size_t)brow * Asz;
                const unsigned int* mrow = d_mask + (size_t)brow * (Asz / 32);
                float best = __int_as_float(0xff800000);
                int bidx = -1;
#pragma unroll
                for (int nt = 0; nt < 8; nt++) {
#pragma unroll
                    for (int e = 0; e < 2; e++) {
                        const int a = bn + wn * 64 + nt * 8 + tg * 2 + e;
                        bool valid;
                        if (j == 0) valid = (xr[a] != 0.0f);
                        else        valid = (a == 0) || ((mrow[a >> 5] >> (a & 31)) & 1u);
                        if (!valid) continue;
                        float v = acc[mt][nt][rh * 2 + e] + bias[a];
                        v += gumbel_at((unsigned long long)brow * Asz + a, sk0, sk1);
                        if (v > best || (v == best && a < bidx)) { best = v; bidx = a; }
                    }
                }
                if (bidx >= 0) {
                    unsigned long long pack =
                        ((unsigned long long)ford(best) << 32) |
                        (unsigned long long)(0xFFFFFFFFu - (unsigned int)bidx);
                    atomicMax(&cand[(size_t)brow * CAND_COLS + candCol], pack);
                }
            }
        }
    }
}

// Persistent dual-target GEMM with dynamic work queue; per-target A operand.
// Target 2 does argmax epilogue iff cand != nullptr.
__global__ void __launch_bounds__(256, 2)
gemm_persist(const __half* __restrict__ A1hi, const __half* __restrict__ A1lo,
             const __half* __restrict__ B1h, const __half* __restrict__ B1l,
             const float* __restrict__ bias1, float* __restrict__ C1, int N1,
             const __half* __restrict__ A2hi, const __half* __restrict__ A2lo,
             const __half* __restrict__ B2h, const __half* __restrict__ B2l,
             const float* __restrict__ bias2, float* __restrict__ C2, int N2,
             int K, int gridX, int xsplit, int numTiles, int slot,
             unsigned long long* cand, const float* __restrict__ x_,
             int j, unsigned int sk0, unsigned int sk1)
{
    extern __shared__ char smraw[];
    __shared__ int s_t;
    for (;;) {
        if (threadIdx.x == 0)
            s_t = (int)atomicAdd(&d_qcounter[slot], 1u);
        __syncthreads();
        const int t = s_t;
        __syncthreads();
        if (t >= numTiles) break;
        const int bx = t % gridX;
        const int by = t / gridX;
        if (bx < xsplit)
            gemm_core(A1hi, A1lo, B1h, B1l, bias1, C1, N1, K,
                      by * BM, bx * BN, smraw,
                      nullptr, 0, nullptr, 0, 0u, 0u);
        else
            gemm_core(A2hi, A2lo, B2h, B2l, bias2, C2, N2, K,
                      by * BM, (bx - xsplit) * BN, smraw,
                      cand, bx - xsplit, x_, j, sk0, sk1);
        __syncthreads();
    }
}

// ======================= elementwise kernels ==============================
#define NW_ (G3H * Hsz)
#define NHW_ (Asz * Hsz)
#define BH_ (Bsz * Hsz)
#define SPLIT_TOTAL (2 * NW_ + NHW_ + BH_ + NHW_)

__global__ void split_all_kernel(
    const float* __restrict__ w_ih, const float* __restrict__ w_hh,
    const float* __restrict__ head_w, const float* __restrict__ cls,
    const float* __restrict__ ae_w)
{
    int i = blockIdx.x * blockDim.x + threadIdx.x;
    if (i >= SPLIT_TOTAL) return;
    const float* src; __half *hi, *lo; int off;
    if (i < NW_)                       { src = w_ih;  hi = d_wih_hi; lo = d_wih_lo; off = i; }
    else if (i < 2 * NW_)              { src = w_hh;  hi = d_whh_hi; lo = d_whh_lo; off = i - NW_; }
    else if (i < 2 * NW_ + NHW_)       { src = head_w; hi = d_hw_hi; lo = d_hw_lo;  off = i - 2 * NW_; }
    else if (i < 2 * NW_ + NHW_ + BH_) { src = cls;   hi = d_cls_hi; lo = d_cls_lo; off = i - 2 * NW_ - NHW_; }
    else                               { src = ae_w;  hi = d_a_hi;  lo = d_a_lo;   off = i - 2 * NW_ - NHW_ - BH_; }
    __half h, l; split_f16(src[off], h, l);
    hi[off] = h; lo[off] = l;
}

__global__ void init_mask_kernel(const float* __restrict__ x_, int nwords)
{
    int w = blockIdx.x * blockDim.x + threadIdx.x;
    if (w >= nwords) return;
    if (w < 8) d_qcounter[w] = 0u;
    if (w < Bsz * CAND_COLS) d_cand[w] = 0ULL;
    const float4* xr = (const float4*)(x_ + ((size_t)(w >> 7) * Asz + (w & 127) * 32));
    unsigned int bits = 0;
#pragma unroll
    for (int q = 0; q < 8; q++) {
        float4 v = xr[q];
        if (v.x != 0.0f) bits |= (1u << (q * 4 + 0));
        if (v.y != 0.0f) bits |= (1u << (q * 4 + 1));
        if (v.z != 0.0f) bits |= (1u << (q * 4 + 2));
        if (v.w != 0.0f) bits |= (1u << (q * 4 + 3));
    }
    d_mask[w] = bits;
}

// Step 0: h_prev = 0 -> gh = b_hh exactly; h = (1-z)*n.  Writes h + fp16 split.
__global__ void gru_step0_kernel(const float* __restrict__ b_hh, int n)
{
    int i = blockIdx.x * blockDim.x + threadIdx.x;
    if (i >= n) return;
    int b = i / Hsz, k = i - b * Hsz;
    const float* gg = d_Gcls + (size_t)b * G3H;
    float ir = gg[k], iz = gg[Hsz + k], inn = gg[2 * Hsz + k];
    float hr = b_hh[k], hz = b_hh[Hsz + k], hn = b_hh[2 * Hsz + k];
    float r = 1.f / (1.f + expf(-(ir + hr)));
    float z = 1.f / (1.f + expf(-(iz + hz)));
    float nn = tanhf(inn + r * hn);
    float hv = (1.f - z) * nn;
    d_h[i] = hv;
    __half h_, l_; split_f16(hv, h_, l_);
    d_a_hi[i] = h_; d_a_lo[i] = l_;
}

// ---------------- candidate reduce + one-hot + fused GRU ------------------
__global__ __launch_bounds__(256) void select_gru_kernel(
    float* __restrict__ out, int j, int doGru)
{
    int b = blockIdx.x;
    int t = threadIdx.x;
    __shared__ int s_sel;

    if (t < 32) {
        unsigned long long pk = d_cand[(size_t)b * CAND_COLS + t];
        d_cand[(size_t)b * CAND_COLS + t] = 0ULL;   // reset for next step/replay
#pragma unroll
        for (int off = 16; off > 0; off >>= 1) {
            unsigned long long o = __shfl_down_sync(0xFFFFFFFFu, pk, off);
            if (o > pk) pk = o;
        }
        if (t == 0) {
            int sel;
            bool done = (j > 0) && (d_idx[(j - 1) * Bsz + b] == 0);
            if (done || pk == 0ULL) sel = 0;
            else sel = (int)(0xFFFFFFFFu - (unsigned int)(pk & 0xFFFFFFFFu));
            s_sel = sel;
            d_idx[j * Bsz + b] = sel;
            d_mask[(size_t)b * (Asz / 32) + (sel >> 5)] &= ~(1u << (sel & 31));
        }
    }
    __syncthreads();
    const int sel = s_sel;

    // write the full one-hot row (out is poisoned, must initialize)
    float4* orow4 = (float4*)(out + ((size_t)b * Lsz + j) * Asz);
    float4 z4 = make_float4(0.f, 0.f, 0.f, 0.f);
    for (int a4 = t; a4 < Asz / 4; a4 += 256) orow4[a4] = z4;
    __syncthreads();   // zeroing must complete before the 1.0 scatter
    if (t == 0) ((float*)orow4)[sel] = 1.0f;

    // ---- fused GRU update for row b (next step's h) ----
    if (doGru) {
        const float* gg = d_Gcls + (size_t)b * G3H;
        const float* ap = d_AEp + (size_t)sel * G3H;
        const float* gh = d_gh + (size_t)b * G3H;
        for (int k = t; k < Hsz; k += 256) {
            float ir = gg[k] + ap[k];
            float iz = gg[Hsz + k] + ap[Hsz + k];
            float inn = gg[2 * Hsz + k] + ap[2 * Hsz + k];
            float hr = gh[k], hz = gh[Hsz + k], hn = gh[2 * Hsz + k];
            float r = 1.f / (1.f + expf(-(ir + hr)));
            float z = 1.f / (1.f + expf(-(iz + hz)));
            float nn = tanhf(inn + r * hn);
            size_t i = (size_t)b * Hsz + k;
            float hv = (1.f - z) * nn + z * d_h[i];
            d_h[i] = hv;
            __half h_, l_; split_f16(hv, h_, l_);
            d_a_hi[i] = h_; d_a_lo[i] = l_;
        }
    }
}

// ======================= launch ===========================================
extern "C" void kernel_launch(void* const* d_in, const int* in_sizes, int n_in,
                              void* d_out, int out_size)
{
    const float* cls    = (const float*)d_in[0];
    const float* x_     = (const float*)d_in[1];
    const float* w_ih   = (const float*)d_in[2];
    const float* w_hh   = (const float*)d_in[3];
    const float* b_ih   = (const float*)d_in[4];
    const float* b_hh   = (const float*)d_in[5];
    const float* head_w = (const float*)d_in[6];
    const float* head_b = (const float*)d_in[7];
    const float* ae_w   = (const float*)d_in[8];
    float* out = (float*)d_out;

    cudaFuncSetAttribute(gemm_persist, cudaFuncAttributeMaxDynamicSharedMemorySize, GEMM_SMEM);

    __half *p_wih_hi, *p_wih_lo, *p_whh_hi, *p_whh_lo, *p_hw_hi, *p_hw_lo;
    __half *p_a_hi, *p_a_lo, *p_cls_hi, *p_cls_lo;
    float *p_Gcls, *p_AEp, *p_gh, *p_h;
    unsigned long long* p_cand;
    cudaGetSymbolAddress((void**)&p_wih_hi, d_wih_hi);
    cudaGetSymbolAddress((void**)&p_wih_lo, d_wih_lo);
    cudaGetSymbolAddress((void**)&p_whh_hi, d_whh_hi);
    cudaGetSymbolAddress((void**)&p_whh_lo, d_whh_lo);
    cudaGetSymbolAddress((void**)&p_hw_hi,  d_hw_hi);
    cudaGetSymbolAddress((void**)&p_hw_lo,  d_hw_lo);
    cudaGetSymbolAddress((void**)&p_a_hi,   d_a_hi);
    cudaGetSymbolAddress((void**)&p_a_lo,   d_a_lo);
    cudaGetSymbolAddress((void**)&p_cls_hi, d_cls_hi);
    cudaGetSymbolAddress((void**)&p_cls_lo, d_cls_lo);
    cudaGetSymbolAddress((void**)&p_Gcls,   d_Gcls);
    cudaGetSymbolAddress((void**)&p_AEp,    d_AEp);
    cudaGetSymbolAddress((void**)&p_gh,     d_gh);
    cudaGetSymbolAddress((void**)&p_h,      d_h);
    cudaGetSymbolAddress((void**)&p_cand,   d_cand);

    // JAX key chain
    unsigned int k0 = 0u, k1 = 42u;
    unsigned int sub[Lsz][2];
    for (int j = 0; j < Lsz; j++) {
#if GUMBEL_PARTITIONABLE
        unsigned int nk0, nk1, s0, s1;
        threefry2x32(k0, k1, 0u, 0u, nk0, nk1);
        threefry2x32(k0, k1, 0u, 1u, s0, s1);
        sub[j][0] = s0; sub[j][1] = s1; k0 = nk0; k1 = nk1;
#else
        unsigned int a0, a1, c0, c1;
        threefry2x32(k0, k1, 0u, 2u, a0, a1);
        threefry2x32(k0, k1, 1u, 3u, c0, c1);
        sub[j][0] = a1; sub[j][1] = c1;
        k0 = a0; k1 = c0;
#endif
    }

    const int BH = Bsz * Hsz;

    init_mask_kernel<<<(Bsz * Asz / 32 + 255) / 256, 256>>>(x_, Bsz * Asz / 32);
    split_all_kernel<<<(SPLIT_TOTAL + 255) / 256, 256>>>(w_ih, w_hh, head_w, cls, ae_w);

    const int gxGates = G3H / BN;               // 18
    const int gxHead = Asz / BN;                // 32
    const int gxDual = gxGates + gxHead;        // 50
    const int tHead = gxHead * (Bsz / BM);      // 1024
    const int tDual = gxDual * (Bsz / BM);      // 1600
    const int tPre = 2 * gxGates * (Bsz / BM);  // 1152

    // Merged precompute (slot 0): G_cls and AE_proj (both normal epilogue)
    gemm_persist<<<NPERSIST, 256, GEMM_SMEM>>>(
        p_cls_hi, p_cls_lo, p_wih_hi, p_wih_lo, b_ih,    p_Gcls, G3H,
        p_a_hi,   p_a_lo,   p_wih_hi, p_wih_lo, nullptr, p_AEp,  G3H,
        Hsz, 2 * gxGates, gxGates, tPre, 0,
        nullptr, nullptr, 0, 0u, 0u);

    // Step 0 (h + fp16 split; overwrites d_a after AE_proj is done)
    gru_step0_kernel<<<(BH + 255) / 256, 256>>>(b_hh, BH);

    for (int j = 0; j < Lsz; j++) {
        if (j < Lsz - 1) {
            // target1: gh (normal); target2: head with fused argmax
            gemm_persist<<<NPERSIST, 256, GEMM_SMEM>>>(
                p_a_hi, p_a_lo, p_whh_hi, p_whh_lo, b_hh,   p_gh,   G3H,
                p_a_hi, p_a_lo, p_hw_hi,  p_hw_lo,  head_b, nullptr, Asz,
                Hsz, gxDual, gxGates, tDual, 1 + j,
                p_cand, x_, j, sub[j][0], sub[j][1]);
        } else {
            // head only, fused argmax (xsplit = 0 -> all tiles target2)
            gemm_persist<<<NPERSIST, 256, GEMM_SMEM>>>(
                p_a_hi, p_a_lo, p_hw_hi, p_hw_lo, head_b, nullptr, Asz,
                p_a_hi, p_a_lo, p_hw_hi, p_hw_lo, head_b, nullptr, Asz,
                Hsz, gxHead, 0, tHead, 4,
                p_cand, x_, j, sub[j][0], sub[j][1]);
        }
        select_gru_kernel<<<Bsz, 256>>>(out, j, (j < Lsz - 1) ? 1 : 0);
    }
}

// round 17
// speedup vs baseline: 1.1775x; 1.1775x over previous
#include <cuda_runtime.h>
#include <cuda_fp16.h>
#include <cstdint>
#include <math.h>

#define Bsz 4096
#define Asz 4096
#define Hsz 768
#define Lsz 4
#define G3H (3 * Hsz)   // 2304

#define GUMBEL_PARTITIONABLE 1

// ======================= device scratch ===================================
__device__ __half d_wih_hi[(size_t)G3H * Hsz];
__device__ __half d_wih_lo[(size_t)G3H * Hsz];
__device__ __half d_whh_hi[(size_t)G3H * Hsz];
__device__ __half d_whh_lo[(size_t)G3H * Hsz];
__device__ __half d_hw_hi[(size_t)Asz * Hsz];
__device__ __half d_hw_lo[(size_t)Asz * Hsz];
__device__ __half d_a_hi[(size_t)Asz * Hsz];    // aew split, then h split
__device__ __half d_a_lo[(size_t)Asz * Hsz];
__device__ __half d_cls_hi[(size_t)Bsz * Hsz];  // cls split
__device__ __half d_cls_lo[(size_t)Bsz * Hsz];
__device__ float d_Gcls[(size_t)Bsz * G3H];
__device__ float d_AEp[(size_t)Asz * G3H];
__device__ float d_gh[(size_t)Bsz * G3H];
__device__ float d_h[(size_t)Bsz * Hsz];
__device__ float d_logits[(size_t)Bsz * Asz];
__device__ unsigned int d_mask[(size_t)Bsz * Asz / 32];
__device__ int d_idx[Lsz * Bsz];
__device__ unsigned int d_qcounter[8];   // persistent-GEMM work queues

// ======================= threefry2x32 =====================================
__host__ __device__ __forceinline__ void threefry2x32(
    unsigned int k0, unsigned int k1, unsigned int x0, unsigned int x1,
    unsigned int& o0, unsigned int& o1)
{
    unsigned int ks0 = k0, ks1 = k1, ks2 = k0 ^ k1 ^ 0x1BD11BDAu;
    x0 += ks0; x1 += ks1;
#define TF_RND(r) { x0 += x1; x1 = (x1 << (r)) | (x1 >> (32 - (r))); x1 ^= x0; }
    TF_RND(13) TF_RND(15) TF_RND(26) TF_RND(6)
    x0 += ks1; x1 += ks2 + 1u;
    TF_RND(17) TF_RND(29) TF_RND(16) TF_RND(24)
    x0 += ks2; x1 += ks0 + 2u;
    TF_RND(13) TF_RND(15) TF_RND(26) TF_RND(6)
    x0 += ks0; x1 += ks1 + 3u;
    TF_RND(17) TF_RND(29) TF_RND(16) TF_RND(24)
    x0 += ks1; x1 += ks2 + 4u;
    TF_RND(13) TF_RND(15) TF_RND(26) TF_RND(6)
    x0 += ks2; x1 += ks0 + 5u;
#undef TF_RND
    o0 = x0; o1 = x1;
}

// ======================= fp16 hi/lo split =================================
__device__ __forceinline__ void split_f16(float x, __half& hi, __half& lo)
{
    __half h = __float2half_rn(x);
    float hf = __half2float(h);
    hi = h;
    lo = __float2half_rn(x - hf);
}

// ======================= fp16x2 mma.sync GEMM (LDSM frags) ================
#define BM 128
#define BN 128
#define BKc 16
#define NSTG 4
#define LDW 12                          // smem row stride words (48 B)
#define AST (128 * LDW * 4)             // 6144 B per array per stage
#define STG_BYTES (4 * AST)             // 24576 B
#define GEMM_SMEM (NSTG * STG_BYTES)    // 98304 B
#define NPERSIST 296                    // 148 SMs x 2 CTAs

#define CP_ASYNC16(dst_u32, src_ptr) \
    asm volatile("cp.async.cg.shared.global [%0], [%1], 16;" :: "r"(dst_u32), "l"(src_ptr) : "memory")
#define CP_COMMIT() asm volatile("cp.async.commit_group;" ::: "memory")
#define CP_WAIT(n)  asm volatile("cp.async.wait_group %0;" :: "n"(n) : "memory")

#define LDSM_X4(r0, r1, r2, r3, addr) \
    asm volatile("ldmatrix.sync.aligned.m8n8.x4.shared.b16 {%0,%1,%2,%3}, [%4];" \
        : "=r"(r0), "=r"(r1), "=r"(r2), "=r"(r3) : "r"(addr))

#define MMA_F16(c, a, b) \
    asm("mma.sync.aligned.m16n8k16.row.col.f32.f16.f16.f32 " \
        "{%0,%1,%2,%3}, {%4,%5,%6,%7}, {%8,%9}, {%0,%1,%2,%3};" \
        : "+f"((c)[0]), "+f"((c)[1]), "+f"((c)[2]), "+f"((c)[3]) \
        : "r"((a)[0]), "r"((a)[1]), "r"((a)[2]), "r"((a)[3]), \
          "r"((b)[0]), "r"((b)[1]))

__device__ __forceinline__ void gemm_core(
    const __half* __restrict__ Ahi, const __half* __restrict__ Alo,
    const __half* __restrict__ Bhi, const __half* __restrict__ Blo,
    const float* __restrict__ bias, float* __restrict__ C,
    int N, int K, int bm, int bn, char* smraw)
{
    const int tid = threadIdx.x;
    const int wid = tid >> 5, lane = tid & 31;
    const int wm = wid >> 1;
    const int wn = wid & 1;
    const int g = lane >> 2;
    const int tg = lane & 3;
    const int NC = K / BKc;

    uint32_t smb;
    asm("{ .reg .u64 t; cvta.to.shared.u64 t, %1; cvt.u32.u64 %0, t; }"
        : "=r"(smb) : "l"(smraw));

    const uint32_t aBase = smb
        + (uint32_t)((wm * 32 + (lane & 15)) * (LDW * 4))
        + (uint32_t)((lane >> 4) * 16);
    const uint32_t bBase = smb + 2 * AST
        + (uint32_t)((wn * 64 + ((lane >> 4) << 3) + (lane & 7)) * (LDW * 4))
        + (uint32_t)(((lane >> 3) & 1) << 4);

    float acc[2][8][4];
#pragma unroll
    for (int i = 0; i < 2; i++)
#pragma unroll
        for (int jj = 0; jj < 8; jj++)
#pragma unroll
            for (int k = 0; k < 4; k++) acc[i][jj][k] = 0.f;

    const int rr = tid >> 1;
    const int qq = tid & 1;

#pragma unroll
    for (int pc = 0; pc < 2; pc++) {
        const int k0 = pc * BKc;
        const uint32_t sbase = smb + pc * STG_BYTES + (uint32_t)(rr * (LDW * 4) + qq * 16);
        const size_t ga = (size_t)(bm + rr) * K + k0 + qq * 8;
        const size_t gb = (size_t)(bn + rr) * K + k0 + qq * 8;
        CP_ASYNC16(sbase,           Ahi + ga);
        CP_ASYNC16(sbase + AST,     Alo + ga);
        CP_ASYNC16(sbase + 2 * AST, Bhi + gb);
        CP_ASYNC16(sbase + 3 * AST, Blo + gb);
        CP_COMMIT();
    }

    for (int c = 0; c < NC; ++c) {
        if (c + 2 < NC) {
            const int k0 = (c + 2) * BKc;
            const int st = (c + 2) & 3;
            const uint32_t sbase = smb + st * STG_BYTES + (uint32_t)(rr * (LDW * 4) + qq * 16);
            const size_t ga = (size_t)(bm + rr) * K + k0 + qq * 8;
            const size_t gb = (size_t)(bn + rr) * K + k0 + qq * 8;
            CP_ASYNC16(sbase,           Ahi + ga);
            CP_ASYNC16(sbase + AST,     Alo + ga);
            CP_ASYNC16(sbase + 2 * AST, Bhi + gb);
            CP_ASYNC16(sbase + 3 * AST, Blo + gb);
            CP_COMMIT();
            CP_WAIT(2);
        } else if (c + 2 == NC) {
            CP_WAIT(1);
        } else {
            CP_WAIT(0);
        }
        __syncthreads();

        const uint32_t stOff = (uint32_t)((c & 3) * STG_BYTES);
        const uint32_t aA = aBase + stOff;
        const uint32_t bA = bBase + stOff;

        uint32_t ahi[2][4], alo[2][4];
        LDSM_X4(ahi[0][0], ahi[0][1], ahi[0][2], ahi[0][3], aA);
        LDSM_X4(ahi[1][0], ahi[1][1], ahi[1][2], ahi[1][3], aA + 16 * (LDW * 4));
        LDSM_X4(alo[0][0], alo[0][1], alo[0][2], alo[0][3], aA + AST);
        LDSM_X4(alo[1][0], alo[1][1], alo[1][2], alo[1][3], aA + AST + 16 * (LDW * 4));

#pragma unroll
        for (int hb = 0; hb < 2; hb++) {
            uint32_t bhi[4][2], blo[4][2];
            const uint32_t bh0 = bA + (uint32_t)(hb * 32 * (LDW * 4));
            LDSM_X4(bhi[0][0], bhi[0][1], bhi[1][0], bhi[1][1], bh0);
            LDSM_X4(bhi[2][0], bhi[2][1], bhi[3][0], bhi[3][1], bh0 + 16 * (LDW * 4));
            LDSM_X4(blo[0][0], blo[0][1], blo[1][0], blo[1][1], bh0 + AST);
            LDSM_X4(blo[2][0], blo[2][1], blo[3][0], blo[3][1], bh0 + AST + 16 * (LDW * 4));
#pragma unroll
            for (int mt = 0; mt < 2; mt++)
#pragma unroll
                for (int nt = 0; nt < 4; nt++)
                    MMA_F16(acc[mt][hb * 4 + nt], ahi[mt], blo[nt]);
#pragma unroll
            for (int mt = 0; mt < 2; mt++)
#pragma unroll
                for (int nt = 0; nt < 4; nt++)
                    MMA_F16(acc[mt][hb * 4 + nt], alo[mt], bhi[nt]);
#pragma unroll
            for (int mt = 0; mt < 2; mt++)
#pragma unroll
                for (int nt = 0; nt < 4; nt++)
                    MMA_F16(acc[mt][hb * 4 + nt], ahi[mt], bhi[nt]);
        }
    }

    // ---- epilogue ----
#pragma unroll
    for (int mt = 0; mt < 2; mt++) {
        const int r0 = bm + wm * 32 + mt * 16 + g;
#pragma unroll
        for (int nt = 0; nt < 8; nt++) {
            const int n0 = bn + wn * 64 + nt * 8 + tg * 2;
            float bx = 0.f, by = 0.f;
            if (bias) { bx = bias[n0]; by = bias[n0 + 1]; }
            float2 v0 = make_float2(acc[mt][nt][0] + bx, acc[mt][nt][1] + by);
            float2 v1 = make_float2(acc[mt][nt][2] + bx, acc[mt][nt][3] + by);
            *(float2*)(C + (size_t)r0 * N + n0) = v0;
            *(float2*)(C + (size_t)(r0 + 8) * N + n0) = v1;
        }
    }
}

// Persistent dual-target GEMM with dynamic work queue; per-target A operand.
__global__ void __launch_bounds__(256, 2)
gemm_persist(const __half* __restrict__ A1hi, const __half* __restrict__ A1lo,
             const __half* __restrict__ B1h, const __half* __restrict__ B1l,
             const float* __restrict__ bias1, float* __restrict__ C1, int N1,
             const __half* __restrict__ A2hi, const __half* __restrict__ A2lo,
             const __half* __restrict__ B2h, const __half* __restrict__ B2l,
             const float* __restrict__ bias2, float* __restrict__ C2, int N2,
             int K, int gridX, int xsplit, int numTiles, int slot)
{
    extern __shared__ char smraw[];
    __shared__ int s_t;
    for (;;) {
        if (threadIdx.x == 0)
            s_t = (int)atomicAdd(&d_qcounter[slot], 1u);
        __syncthreads();
        const int t = s_t;
        __syncthreads();
        if (t >= numTiles) break;
        const int bx = t % gridX;
        const int by = t / gridX;
        if (bx < xsplit)
            gemm_core(A1hi, A1lo, B1h, B1l, bias1, C1, N1, K,
                      by * BM, bx * BN, smraw);
        else
            gemm_core(A2hi, A2lo, B2h, B2l, bias2, C2, N2, K,
                      by * BM, (bx - xsplit) * BN, smraw);
        __syncthreads();
    }
}

// ======================= elementwise kernels ==============================
#define NW_ (G3H * Hsz)
#define NHW_ (Asz * Hsz)
#define BH_ (Bsz * Hsz)
#define SPLIT_TOTAL (2 * NW_ + NHW_ + BH_ + NHW_)

__global__ void split_all_kernel(
    const float* __restrict__ w_ih, const float* __restrict__ w_hh,
    const float* __restrict__ head_w, const float* __restrict__ cls,
    const float* __restrict__ ae_w)
{
    int i = blockIdx.x * blockDim.x + threadIdx.x;
    if (i >= SPLIT_TOTAL) return;
    const float* src; __half *hi, *lo; int off;
    if (i < NW_)                       { src = w_ih;  hi = d_wih_hi; lo = d_wih_lo; off = i; }
    else if (i < 2 * NW_)              { src = w_hh;  hi = d_whh_hi; lo = d_whh_lo; off = i - NW_; }
    else if (i < 2 * NW_ + NHW_)       { src = head_w; hi = d_hw_hi; lo = d_hw_lo;  off = i - 2 * NW_; }
    else if (i < 2 * NW_ + NHW_ + BH_) { src = cls;   hi = d_cls_hi; lo = d_cls_lo; off = i - 2 * NW_ - NHW_; }
    else                               { src = ae_w;  hi = d_a_hi;  lo = d_a_lo;   off = i - 2 * NW_ - NHW_ - BH_; }
    __half h, l; split_f16(src[off], h, l);
    hi[off] = h; lo[off] = l;
}

__global__ void init_mask_kernel(const float* __restrict__ x_, int nwords)
{
    int w = blockIdx.x * blockDim.x + threadIdx.x;
    if (w >= nwords) return;
    if (w < 8) d_qcounter[w] = 0u;
    const float4* xr = (const float4*)(x_ + ((size_t)(w >> 7) * Asz + (w & 127) * 32));
    unsigned int bits = 0;
#pragma unroll
    for (int q = 0; q < 8; q++) {
        float4 v = xr[q];
        if (v.x != 0.0f) bits |= (1u << (q * 4 + 0));
        if (v.y != 0.0f) bits |= (1u << (q * 4 + 1));
        if (v.z != 0.0f) bits |= (1u << (q * 4 + 2));
        if (v.w != 0.0f) bits |= (1u << (q * 4 + 3));
    }
    d_mask[w] = bits;
}

// Step 0: h_prev = 0 -> gh = b_hh exactly; h = (1-z)*n.  Writes h + fp16 split.
__global__ void gru_step0_kernel(const float* __restrict__ b_hh, int n)
{
    int i = blockIdx.x * blockDim.x + threadIdx.x;
    if (i >= n) return;
    int b = i / Hsz, k = i - b * Hsz;
    const float* gg = d_Gcls + (size_t)b * G3H;
    float ir = gg[k], iz = gg[Hsz + k], inn = gg[2 * Hsz + k];
    float hr = b_hh[k], hz = b_hh[Hsz + k], hn = b_hh[2 * Hsz + k];
    float r = 1.f / (1.f + expf(-(ir + hr)));
    float z = 1.f / (1.f + expf(-(iz + hz)));
    float nn = tanhf(inn + r * hn);
    float hv = (1.f - z) * nn;
    d_h[i] = hv;
    __half h_, l_; split_f16(hv, h_, l_);
    d_a_hi[i] = h_; d_a_lo[i] = l_;
}

// ---------------- fused selection + GRU update ----------------------------
// Validity always from the mask bitset (at j==0 it is pristine x_!=0; the
// empty-row case falls through to the sel=0 sentinel, matching the reference).
__global__ __launch_bounds__(256) void select_gru_kernel(
    float* __restrict__ out, int j, unsigned int sk0, unsigned int sk1, int doGru)
{
    int b = blockIdx.x;
    int t = threadIdx.x;
    __shared__ float sv[256];
    __shared__ int si[256];
    __shared__ int s_done;
    __shared__ int s_sel;

    bool done = false;
    if (j > 0) {
        if (t == 0) s_done = (d_idx[(j - 1) * Bsz + b] == 0);
        __syncthreads();
        done = (s_done != 0);
    }

    if (!done) {
        float best = __int_as_float(0xff800000);
        int bidx = 0x7fffffff;
        const float* lrow = d_logits + (size_t)b * Asz;
        const unsigned int* mrow = d_mask + (size_t)b * (Asz / 32);

        // each thread handles mask words t, t+256/32... -> words t..; 128 words total
        for (int w = t; w < Asz / 32; w += 256) {
            unsigned int bits = mrow[w];
            if (j > 0 && w == 0) bits |= 1u;      // a==0 always valid for j>0
            while (bits) {
                int bit = __ffs(bits) - 1;
                bits &= bits - 1;
                int a = w * 32 + bit;

                unsigned long long p = (unsigned long long)b * Asz + (unsigned long long)a;
                unsigned int y0, y1, rb;
#if GUMBEL_PARTITIONABLE
                threefry2x32(sk0, sk1, (unsigned int)(p >> 32), (unsigned int)p, y0, y1);
                rb = y0 ^ y1;
#else
                const unsigned long long NH = (unsigned long long)Bsz * Asz / 2;
                if (p < NH) { threefry2x32(sk0, sk1, (unsigned int)p, (unsigned int)(p + NH), y0, y1); rb = y0; }
                else        { threefry2x32(sk0, sk1, (unsigned int)(p - NH), (unsigned int)p, y0, y1); rb = y1; }
#endif
                float u = __uint_as_float((rb >> 9) | 0x3f800000u) - 1.0f;
                u = fmaxf(u, 1.17549435e-38f);
                float gmb = -logf(-logf(u));
                float v = lrow[a] + gmb;
                if (v > best || (v == best && a < bidx)) { best = v; bidx = a; }
            }
        }

        sv[t] = best; si[t] = bidx;
        __syncthreads();
        for (int s = 128; s > 0; s >>= 1) {
            if (t < s) {
                float v2 = sv[t + s]; int i2 = si[t + s];
                if (v2 > sv[t] || (v2 == sv[t] && i2 < si[t])) { sv[t] = v2; si[t] = i2; }
            }
            __syncthreads();
        }
        if (t == 0) s_sel = (si[0] == 0x7fffffff) ? 0 : si[0];
    } else {
        if (t == 0) s_sel = 0;
    }
    __syncthreads();
    const int sel = s_sel;

    // write the full one-hot row (out is poisoned, must initialize)
    float4* orow4 = (float4*)(out + ((size_t)b * Lsz + j) * Asz);
    float4 z4 = make_float4(0.f, 0.f, 0.f, 0.f);
    for (int a4 = t; a4 < Asz / 4; a4 += 256) orow4[a4] = z4;
    __syncthreads();   // zeroing must complete before the 1.0 scatter
    if (t == 0) {
        ((float*)orow4)[sel] = 1.0f;
        d_idx[j * Bsz + b] = sel;
        d_mask[(size_t)b * (Asz / 32) + (sel >> 5)] &= ~(1u << (sel & 31));
    }

    // ---- fused GRU update for row b (next step's h) ----
    if (doGru) {
        const float* gg = d_Gcls + (size_t)b * G3H;
        const float* ap = d_AEp + (size_t)sel * G3H;
        const float* gh = d_gh + (size_t)b * G3H;
        for (int k = t; k < Hsz; k += 256) {
            float ir = gg[k] + ap[k];
            float iz = gg[Hsz + k] + ap[Hsz + k];
            float inn = gg[2 * Hsz + k] + ap[2 * Hsz + k];
            float hr = gh[k], hz = gh[Hsz + k], hn = gh[2 * Hsz + k];
            float r = 1.f / (1.f + expf(-(ir + hr)));
            float z = 1.f / (1.f + expf(-(iz + hz)));
            float nn = tanhf(inn + r * hn);
            size_t i = (size_t)b * Hsz + k;
            float hv = (1.f - z) * nn + z * d_h[i];
            d_h[i] = hv;
            __half h_, l_; split_f16(hv, h_, l_);
            d_a_hi[i] = h_; d_a_lo[i] = l_;
        }
    }
}

// ======================= launch ===========================================
extern "C" void kernel_launch(void* const* d_in, const int* in_sizes, int n_in,
                              void* d_out, int out_size)
{
    const float* cls    = (const float*)d_in[0];
    const float* x_     = (const float*)d_in[1];
    const float* w_ih   = (const float*)d_in[2];
    const float* w_hh   = (const float*)d_in[3];
    const float* b_ih   = (const float*)d_in[4];
    const float* b_hh   = (const float*)d_in[5];
    const float* head_w = (const float*)d_in[6];
    const float* head_b = (const float*)d_in[7];
    const float* ae_w   = (const float*)d_in[8];
    float* out = (float*)d_out;

    cudaFuncSetAttribute(gemm_persist, cudaFuncAttributeMaxDynamicSharedMemorySize, GEMM_SMEM);

    __half *p_wih_hi, *p_wih_lo, *p_whh_hi, *p_whh_lo, *p_hw_hi, *p_hw_lo;
    __half *p_a_hi, *p_a_lo, *p_cls_hi, *p_cls_lo;
    float *p_Gcls, *p_AEp, *p_gh, *p_h, *p_logits;
    cudaGetSymbolAddress((void**)&p_wih_hi, d_wih_hi);
    cudaGetSymbolAddress((void**)&p_wih_lo, d_wih_lo);
    cudaGetSymbolAddress((void**)&p_whh_hi, d_whh_hi);
    cudaGetSymbolAddress((void**)&p_whh_lo, d_whh_lo);
    cudaGetSymbolAddress((void**)&p_hw_hi,  d_hw_hi);
    cudaGetSymbolAddress((void**)&p_hw_lo,  d_hw_lo);
    cudaGetSymbolAddress((void**)&p_a_hi,   d_a_hi);
    cudaGetSymbolAddress((void**)&p_a_lo,   d_a_lo);
    cudaGetSymbolAddress((void**)&p_cls_hi, d_cls_hi);
    cudaGetSymbolAddress((void**)&p_cls_lo, d_cls_lo);
    cudaGetSymbolAddress((void**)&p_Gcls,   d_Gcls);
    cudaGetSymbolAddress((void**)&p_AEp,    d_AEp);
    cudaGetSymbolAddress((void**)&p_gh,     d_gh);
    cudaGetSymbolAddress((void**)&p_h,      d_h);
    cudaGetSymbolAddress((void**)&p_logits, d_logits);

    // JAX key chain
    unsigned int k0 = 0u, k1 = 42u;
    unsigned int sub[Lsz][2];
    for (int j = 0; j < Lsz; j++) {
#if GUMBEL_PARTITIONABLE
        unsigned int nk0, nk1, s0, s1;
        threefry2x32(k0, k1, 0u, 0u, nk0, nk1);
        threefry2x32(k0, k1, 0u, 1u, s0, s1);
        sub[j][0] = s0; sub[j][1] = s1; k0 = nk0; k1 = nk1;
#else
        unsigned int a0, a1, c0, c1;
        threefry2x32(k0, k1, 0u, 2u, a0, a1);
        threefry2x32(k0, k1, 1u, 3u, c0, c1);
        sub[j][0] = a1; sub[j][1] = c1;
        k0 = a0; k1 = c0;
#endif
    }

    const int BH = Bsz * Hsz;

    init_mask_kernel<<<(Bsz * Asz / 32 + 255) / 256, 256>>>(x_, Bsz * Asz / 32);
    split_all_kernel<<<(SPLIT_TOTAL + 255) / 256, 256>>>(w_ih, w_hh, head_w, cls, ae_w);

    const int gxGates = G3H / BN;               // 18
    const int gxHead = Asz / BN;                // 32
    const int gxDual = gxGates + gxHead;        // 50
    const int tHead = gxHead * (Bsz / BM);      // 1024
    const int tDual = gxDual * (Bsz / BM);      // 1600
    const int tPre = 2 * gxGates * (Bsz / BM);  // 1152

    // Merged precompute (slot 0): G_cls and AE_proj
    gemm_persist<<<NPERSIST, 256, GEMM_SMEM>>>(
        p_cls_hi, p_cls_lo, p_wih_hi, p_wih_lo, b_ih,    p_Gcls, G3H,
        p_a_hi,   p_a_lo,   p_wih_hi, p_wih_lo, nullptr, p_AEp,  G3H,
        Hsz, 2 * gxGates, gxGates, tPre, 0);

    // Step 0 (h + fp16 split; overwrites d_a after AE_proj is done)
    gru_step0_kernel<<<(BH + 255) / 256, 256>>>(b_hh, BH);

    for (int j = 0; j < Lsz; j++) {
        if (j < Lsz - 1) {
            gemm_persist<<<NPERSIST, 256, GEMM_SMEM>>>(
                p_a_hi, p_a_lo, p_whh_hi, p_whh_lo, b_hh,   p_gh,     G3H,
                p_a_hi, p_a_lo, p_hw_hi,  p_hw_lo,  head_b, p_logits, Asz,
                Hsz, gxDual, gxGates, tDual, 1 + j);
        } else {
            gemm_persist<<<NPERSIST, 256, GEMM_SMEM>>>(
                p_a_hi, p_a_lo, p_hw_hi, p_hw_lo, head_b, p_logits, Asz,
                p_a_hi, p_a_lo, p_hw_hi, p_hw_lo, head_b, p_logits, Asz,
                Hsz, gxHead, 0, tHead, 4);
        }
        select_gru_kernel<<<Bsz, 256>>>(out, j, sub[j][0], sub[j][1],
                                        (j < Lsz - 1) ? 1 : 0);
    }
}